// round 16
// baseline (speedup 1.0000x reference)
#include <cuda_runtime.h>
#include <stdint.h>

#define NN   100001
#define EE   6400000
#define KH   5            // Horner depth: res = sum_{k=0..KH} R^k (c_k r0 + h_k a)
#define CAP  128          // bucket capacity per row; P(overflow) ~ 2e-11/row

// ---- static device scratch (allocation-free) ----
__device__ int    g_cnt[NN];             // per-row edge count
__device__ int2   g_bucket[NN * CAP];    // row-major fixed-capacity CSR: (dj, w-bits)
__device__ float  g_v1[NN];
__device__ float  g_v2[NN];
__device__ float  g_a[NN];               // a_i = sum of weights of edges (i, 0), i != 0
__device__ int    g_c00;                 // count of (0,0) adjacency edges (dv = 1.0 each)
__device__ float  g_ck[KH + 1];          // C(100,k) * 0.9^(100-k)
__device__ float  g_hk[KH + 1];          // sum_{m=k}^{99} s^(99-m) C(m,k) 0.9^(m-k)
__device__ int    g_maxbits;
__device__ int    g_is64;

// zero + dtype detect (JAX x64-disabled silently demotes int64 -> int32;
// int32 viewed as int64 is >= 2^32 unless the hi word is 0, so "all 64
// in range" reliably identifies a true int64 layout).
__global__ void zero_kernel(const void* __restrict__ adj) {
    int i = blockIdx.x * blockDim.x + threadIdx.x;
    if (i < NN) { g_a[i] = 0.0f; g_cnt[i] = 0; }
    if (blockIdx.x == 0 && threadIdx.x == 0) {
        const long long* a64 = (const long long*)adj;
        int ok = 1;
        for (int t = 0; t < 64; ++t) {
            long long v = a64[t];
            if (v < 0 || v >= NN) { ok = 0; break; }
        }
        g_is64 = ok;
        g_c00 = 0;
        g_maxbits = 0;
    }
}

// Single-pass routing + bucket scatter (per reference masking):
//   di==0 && dj==0 -> c00 count (node-0 self weight)
//   di==0 && dj!=0 -> dropped (dv masked to 0)
//   di!=0 && dj==0 -> driving vector a[di] += 0.1*val
//   else           -> bucket edge (dj, 0.1*val) appended to row di
// Plain cached stores: the bucket is re-read 5x by the edge passes and
// must stay L2-resident.
__device__ __forceinline__ void scat_one(int di, int dj, float v) {
    if ((unsigned)di >= NN || (unsigned)dj >= NN) return;
    if (di == 0) {
        if (dj == 0) atomicAdd(&g_c00, 1);
        return;
    }
    if (dj == 0) {
        atomicAdd(&g_a[di], 0.1f * v);
        return;
    }
    int slot = atomicAdd(&g_cnt[di], 1);
    if (slot < CAP)
        g_bucket[(di << 7) + slot] = make_int2(dj, __float_as_int(0.1f * v));
}

// Separate kernels per dtype: keeps register allocation tight for the hot
// int32 path (a merged kernel with a runtime branch inflates regs for the
// union of both paths and cuts scatter occupancy).
__global__ void scatter64_kernel(const long long* __restrict__ adj,
                                 const float* __restrict__ val, int E) {
    if (!g_is64) return;
    int stride = gridDim.x * blockDim.x;
    for (int e = blockIdx.x * blockDim.x + threadIdx.x; e < E; e += stride)
        scat_one((int)adj[e], (int)adj[(long long)E + e], val[e]);
}
__global__ void scatter32_kernel(const int* __restrict__ adj,
                                 const float* __restrict__ val, int E) {
    if (g_is64) return;
    int stride = gridDim.x * blockDim.x;
    for (int e = blockIdx.x * blockDim.x + threadIdx.x; e < E; e += stride)
        scat_one(adj[e], adj[E + e], val[e]);
}

// Parallel exact coefficients (double, multiply-only inner loops).
__global__ void coeff_kernel() {
    __shared__ double inv[101];
    int t = threadIdx.x;
    for (int i = t + 1; i <= 100; i += blockDim.x) inv[i] = 1.0 / (double)i;
    __syncthreads();
    double s = 1.0 + (double)g_c00;
    double inv_s = 1.0 / s;
    if (t <= KH) {
        int k = t;
        double comb = 1.0;
        for (int i = 1; i <= k; ++i) comb *= (double)(100 - i + 1) * inv[i];
        double pw = 1.0;
        for (int i = 0; i < 100 - k; ++i) pw *= 0.9;
        g_ck[k] = (float)(comb * pw);
    } else if (t >= 32 && t <= 32 + KH) {
        int k = t - 32;
        double spow = 1.0;
        for (int i = 0; i < 99 - k; ++i) spow *= s;      // s^(99-k)
        double h = 0.0, Cmk = 1.0, pw = 1.0;
        for (int m = k; m < 100; ++m) {
            h += spow * Cmk * pw;
            Cmk = Cmk * (double)(m + 1) * inv[m + 1 - k];
            pw *= 0.9;
            spow *= inv_s;
        }
        g_hk[k] = (float)h;
    }
}

// Fused Horner step (warp-per-row, plain stores):
//   out[row] = sum_edges w * zin(dj) + c_k + h_k * a[row]   (row >= 1), out[0]=0
// affine=1 (first pass): zin(j) = c_K + h_K * in(j)  (bucket edges have dj>=1).
// domax=1 (last pass):   fold |out[row]| into g_maxbits (no-return REDG.MAX).
__global__ void edge_kernel(const float* __restrict__ in, float* __restrict__ out,
                            int k, int affine, int domax) {
    int w = (blockIdx.x * blockDim.x + threadIdx.x) >> 5;
    int lane = threadIdx.x & 31;
    if (w >= NN) return;
    if (w == 0) { if (lane == 0) out[0] = 0.0f; return; }
    int cnt = g_cnt[w];
    if (cnt > CAP) cnt = CAP;
    const int2* row = g_bucket + (w << 7);
    float cK = g_ck[KH], hK = g_hk[KH];
    float sum = 0.0f;
    for (int e = lane; e < cnt; e += 32) {
        int2 ed = row[e];
        float gv = __ldg(in + ed.x);
        if (affine) gv = fmaf(hK, gv, cK);
        sum = fmaf(__int_as_float(ed.y), gv, sum);
    }
    #pragma unroll
    for (int o = 16; o; o >>= 1) sum += __shfl_xor_sync(0xffffffffu, sum, o);
    if (lane == 0) {
        float r = sum + g_ck[k] + g_hk[k] * g_a[w];
        out[w] = r;
        // |r| >= 0 -> integer-bit compare is order-preserving
        if (domax) atomicMax(&g_maxbits, __float_as_int(fabsf(r)));
    }
}

__global__ void norm_kernel(const float* __restrict__ s, float* __restrict__ out) {
    int i = blockIdx.x * blockDim.x + threadIdx.x;
    if (i < NN) {
        float inv = 1.0f / __int_as_float(g_maxbits);
        out[i] = (i == 0) ? 1.0f : s[i] * inv;
    }
}

extern "C" void kernel_launch(void* const* d_in, const int* in_sizes, int n_in,
                              void* d_out, int out_size) {
    const void*  adj = d_in[0];
    const float* val = (const float*)d_in[1];
    int E = in_sizes[1];
    if (E > EE) E = EE;

    float *v1 = nullptr, *v2 = nullptr, *av = nullptr;
    cudaGetSymbolAddress((void**)&v1, g_v1);
    cudaGetSymbolAddress((void**)&v2, g_v2);
    cudaGetSymbolAddress((void**)&av, g_a);

    const int NB  = (NN + 255) / 256;
    const int NBW = (NN * 32 + 255) / 256;   // warp per row

    zero_kernel<<<NB, 256>>>(adj);
    scatter64_kernel<<<2048, 256>>>((const long long*)adj, val, E);
    scatter32_kernel<<<2048, 256>>>((const int*)adj, val, E);
    coeff_kernel<<<1, 64>>>();

    // Horner: z_K = c_K r0 + h_K a (built inline in first pass);
    //         z_k = R z_{k+1} + c_k r0 + h_k a
    edge_kernel<<<NBW, 256>>>(av, v1, KH - 1, 1, 0);
    float* cur = v1;
    float* nxt = v2;
    for (int k = KH - 2; k >= 0; --k) {
        edge_kernel<<<NBW, 256>>>(cur, nxt, k, 0, k == 0);
        float* t = cur; cur = nxt; nxt = t;
    }

    norm_kernel<<<NB, 256>>>(cur, (float*)d_out);
}

// round 17
// speedup vs baseline: 1.2446x; 1.2446x over previous
#include <cuda_runtime.h>
#include <stdint.h>

#define NN   100001
#define EE   6400000
#define KH   5            // Horner depth: res = sum_{k=0..KH} R^k (c_k r0 + h_k a)
#define CAP  128          // bucket capacity per row; P(overflow) ~ 2e-11/row

// ---- static device scratch (allocation-free) ----
__device__ int    g_cnt[NN];             // per-row edge count
__device__ int2   g_bucket[NN * CAP];    // row-major fixed-capacity CSR: (dj, w-bits)
__device__ float  g_v1[NN];
__device__ float  g_v2[NN];
__device__ float  g_a[NN];               // a_i = sum of weights of edges (i, 0), i != 0
__device__ int    g_c00;                 // count of (0,0) adjacency edges (dv = 1.0 each)
__device__ float  g_ck[KH + 1];          // C(100,k) * 0.9^(100-k)
__device__ float  g_hk[KH + 1];          // sum_{m=k}^{99} s^(99-m) C(m,k) 0.9^(m-k)
__device__ int    g_maxbits;
__device__ int    g_is64;

// zero + dtype detect (JAX x64-disabled silently demotes int64 -> int32;
// int32 viewed as int64 is >= 2^32 unless the hi word is 0, so "all 64
// in range" reliably identifies a true int64 layout).
__global__ void zero_kernel(const void* __restrict__ adj) {
    int i = blockIdx.x * blockDim.x + threadIdx.x;
    if (i < NN) { g_a[i] = 0.0f; g_cnt[i] = 0; }
    if (blockIdx.x == 0 && threadIdx.x == 0) {
        const long long* a64 = (const long long*)adj;
        int ok = 1;
        for (int t = 0; t < 64; ++t) {
            long long v = a64[t];
            if (v < 0 || v >= NN) { ok = 0; break; }
        }
        g_is64 = ok;
        g_c00 = 0;
        g_maxbits = 0;
    }
}

// Single-pass routing + bucket scatter (per reference masking):
//   di==0 && dj==0 -> c00 count; di==0 && dj!=0 -> dropped
//   di!=0 && dj==0 -> a[di] += 0.1*val
//   else           -> bucket edge (dj, 0.1*val) appended to row di
// Plain cached stores: the bucket is re-read 5x and must stay L2-resident.
__device__ __forceinline__ void scat_one(int di, int dj, float v) {
    if ((unsigned)di >= NN || (unsigned)dj >= NN) return;
    if (di == 0) {
        if (dj == 0) atomicAdd(&g_c00, 1);
        return;
    }
    if (dj == 0) {
        atomicAdd(&g_a[di], 0.1f * v);
        return;
    }
    int slot = atomicAdd(&g_cnt[di], 1);
    if (slot < CAP)
        g_bucket[(di << 7) + slot] = make_int2(dj, __float_as_int(0.1f * v));
}

__global__ void scatter64_kernel(const long long* __restrict__ adj,
                                 const float* __restrict__ val, int E) {
    if (!g_is64) return;
    int stride = gridDim.x * blockDim.x;
    for (int e = blockIdx.x * blockDim.x + threadIdx.x; e < E; e += stride)
        scat_one((int)adj[e], (int)adj[(long long)E + e], val[e]);
}
__global__ void scatter32_kernel(const int* __restrict__ adj,
                                 const float* __restrict__ val, int E) {
    if (g_is64) return;
    int stride = gridDim.x * blockDim.x;
    for (int e = blockIdx.x * blockDim.x + threadIdx.x; e < E; e += stride)
        scat_one(adj[e], adj[E + e], val[e]);
}

// Binary exponentiation: ~7-step dependent chain instead of e-step.
__device__ __forceinline__ double dpow(double b, int e) {
    double r = 1.0, p = b;
    while (e) { if (e & 1) r *= p; p *= p; e >>= 1; }
    return r;
}

// Exact series coefficients, latency-parallel: warp k computes
//   h_k = sum_{m=k}^{99} s^(99-m) C(m,k) 0.9^(m-k)   (lanes over m, shfl-reduce)
//   c_k = C(100,k) 0.9^(100-k)                        (lane 0)
// No dependent chain longer than ~7 double multiplies.
__global__ void coeff_kernel() {
    int k = threadIdx.x >> 5;
    int lane = threadIdx.x & 31;
    if (k > KH) return;
    const double kfact_inv[6] = {1.0, 1.0, 0.5, 1.0/6.0, 1.0/24.0, 1.0/120.0};
    double s = 1.0 + (double)g_c00;
    double hsum = 0.0;
    for (int m = k + lane; m < 100; m += 32) {
        double comb = kfact_inv[k];
        for (int i = 0; i < k; ++i) comb *= (double)(m - i);   // C(m,k)*k! terms
        hsum += dpow(s, 99 - m) * comb * dpow(0.9, m - k);
    }
    #pragma unroll
    for (int o = 16; o; o >>= 1) hsum += __shfl_xor_sync(0xffffffffu, hsum, o);
    if (lane == 0) {
        g_hk[k] = (float)hsum;
        double comb = kfact_inv[k];
        for (int i = 0; i < k; ++i) comb *= (double)(100 - i); // C(100,k)
        g_ck[k] = (float)(comb * dpow(0.9, 100 - k));
    }
}

// Fused Horner step (warp-per-row, plain stores):
//   out[row] = sum_edges w * zin(dj) + c_k + h_k * a[row]   (row >= 1), out[0]=0
// affine=1 (first pass): zin(j) = c_K + h_K * in(j)  (bucket edges have dj>=1).
__global__ void edge_kernel(const float* __restrict__ in, float* __restrict__ out,
                            int k, int affine) {
    int w = (blockIdx.x * blockDim.x + threadIdx.x) >> 5;
    int lane = threadIdx.x & 31;
    if (w >= NN) return;
    if (w == 0) { if (lane == 0) out[0] = 0.0f; return; }
    int cnt = g_cnt[w];
    if (cnt > CAP) cnt = CAP;
    const int2* row = g_bucket + (w << 7);
    float cK = g_ck[KH], hK = g_hk[KH];
    float sum = 0.0f;
    for (int e = lane; e < cnt; e += 32) {
        int2 ed = row[e];
        float gv = __ldg(in + ed.x);
        if (affine) gv = fmaf(hK, gv, cK);
        sum = fmaf(__int_as_float(ed.y), gv, sum);
    }
    #pragma unroll
    for (int o = 16; o; o >>= 1) sum += __shfl_xor_sync(0xffffffffu, sum, o);
    if (lane == 0) out[w] = sum + g_ck[k] + g_hk[k] * g_a[w];
}

// Two-stage max reduction: only 512 same-address atomics (the fused
// per-row version serialized 100K REDG.MAX on one address — measured
// +40us; this separate kernel is the proven-fast shape).
__global__ void maxred_kernel(const float* __restrict__ s) {
    __shared__ float smx[8];
    float m = 0.0f;
    int stride = gridDim.x * blockDim.x;
    for (int i = blockIdx.x * blockDim.x + threadIdx.x + 1; i < NN; i += stride)
        m = fmaxf(m, fabsf(s[i]));
    #pragma unroll
    for (int o = 16; o; o >>= 1) m = fmaxf(m, __shfl_xor_sync(0xffffffffu, m, o));
    if ((threadIdx.x & 31) == 0) smx[threadIdx.x >> 5] = m;
    __syncthreads();
    if (threadIdx.x < 32) {
        m = (threadIdx.x < (blockDim.x >> 5)) ? smx[threadIdx.x] : 0.0f;
        #pragma unroll
        for (int o = 16; o; o >>= 1) m = fmaxf(m, __shfl_xor_sync(0xffffffffu, m, o));
        // values >= 0 -> integer-bit compare is order-preserving
        if (threadIdx.x == 0) atomicMax(&g_maxbits, __float_as_int(m));
    }
}

__global__ void norm_kernel(const float* __restrict__ s, float* __restrict__ out) {
    int i = blockIdx.x * blockDim.x + threadIdx.x;
    if (i < NN) {
        float inv = 1.0f / __int_as_float(g_maxbits);
        out[i] = (i == 0) ? 1.0f : s[i] * inv;
    }
}

extern "C" void kernel_launch(void* const* d_in, const int* in_sizes, int n_in,
                              void* d_out, int out_size) {
    const void*  adj = d_in[0];
    const float* val = (const float*)d_in[1];
    int E = in_sizes[1];
    if (E > EE) E = EE;

    float *v1 = nullptr, *v2 = nullptr, *av = nullptr;
    cudaGetSymbolAddress((void**)&v1, g_v1);
    cudaGetSymbolAddress((void**)&v2, g_v2);
    cudaGetSymbolAddress((void**)&av, g_a);

    const int NB  = (NN + 255) / 256;
    const int NBW = (NN * 32 + 255) / 256;   // warp per row

    zero_kernel<<<NB, 256>>>(adj);
    scatter64_kernel<<<2048, 256>>>((const long long*)adj, val, E);
    scatter32_kernel<<<2048, 256>>>((const int*)adj, val, E);
    coeff_kernel<<<1, 32 * (KH + 1)>>>();

    // Horner: z_K = c_K r0 + h_K a (built inline in first pass);
    //         z_k = R z_{k+1} + c_k r0 + h_k a
    edge_kernel<<<NBW, 256>>>(av, v1, KH - 1, 1);
    float* cur = v1;
    float* nxt = v2;
    for (int k = KH - 2; k >= 0; --k) {
        edge_kernel<<<NBW, 256>>>(cur, nxt, k, 0);
        float* t = cur; cur = nxt; nxt = t;
    }

    maxred_kernel<<<512, 256>>>(cur);
    norm_kernel<<<NB, 256>>>(cur, (float*)d_out);
}